// round 1
// baseline (speedup 1.0000x reference)
#include <cuda_runtime.h>
#include <cuda_bf16.h>
#include <math.h>

// ---------------- constants ----------------
#define BATCH 8
#define SLEN 1024
#define EMB 768
#define NH 12
#define HD 64
#define MROWS (BATCH*SLEN)          // 8192

// ---------------- device scratch (no allocations allowed) ----------------
__device__ float g_Q[BATCH*NH*SLEN*HD];
__device__ float g_K[BATCH*NH*SLEN*HD];
__device__ float g_V[BATCH*NH*SLEN*HD];
__device__ float g_AO[MROWS*EMB];
__device__ float g_gate[BATCH*NH*SLEN];
__device__ unsigned char g_bucket[SLEN*SLEN];

// ---------------- bucket table ----------------
// bucket(q,k): rp = k-q; base = (rp>0)*16; a=|rp|;
//   a<8 -> +a ; else += 8 + v, where v = trunc(2*log2(a/8)), capped at 7.
// Exact integer thresholds for v: a>=12 ->1, >=16 ->2, >=23 ->3, >=32 ->4,
//   >=46 ->5, >=64 ->6, >=91 ->7.
__global__ __launch_bounds__(256) void bucket_kernel() {
    int k = blockIdx.x * 256 + threadIdx.x;
    int q = blockIdx.y;
    int rp = k - q;
    int bucket = (rp > 0) ? 16 : 0;
    int a = (rp < 0) ? -rp : rp;
    int add;
    if      (a < 8)  add = a;
    else if (a < 12) add = 8;
    else if (a < 16) add = 9;
    else if (a < 23) add = 10;
    else if (a < 32) add = 11;
    else if (a < 46) add = 12;
    else if (a < 64) add = 13;
    else if (a < 91) add = 14;
    else             add = 15;
    g_bucket[q * SLEN + k] = (unsigned char)(bucket + add);
}

// ---------------- gate kernel ----------------
// g = sigmoid((ql @ gru_W + gru_b).reshape(...,2,4).sum(-1))  -- linear, so
// pre-sum the 8 columns of gru_W into two 64-vectors.
__global__ __launch_bounds__(256) void gate_kernel(
    const float* __restrict__ query,
    const float* __restrict__ gW,     // [64,8]
    const float* __restrict__ gb,     // [8]
    const float* __restrict__ gc)     // [12] (1,H,1,1)
{
    __shared__ float sw0[64], sw1[64];
    int tid = threadIdx.x;
    if (tid < 64) {
        const float* w = gW + tid * 8;
        sw0[tid] = w[0] + w[1] + w[2] + w[3];
        sw1[tid] = w[4] + w[5] + w[6] + w[7];
    }
    __syncthreads();
    float b0 = gb[0] + gb[1] + gb[2] + gb[3];
    float b1 = gb[4] + gb[5] + gb[6] + gb[7];

    int idx = blockIdx.x * 256 + tid;          // (b*12+h)*1024 + s
    int s = idx & (SLEN - 1);
    int h = (idx >> 10) % NH;
    int b = idx / (NH * SLEN);
    const float* q = query + ((size_t)(b * SLEN + s)) * EMB + h * HD;
    float z0 = b0, z1 = b1;
#pragma unroll 8
    for (int d = 0; d < HD; d++) {
        float qv = __ldg(&q[d]);
        z0 += qv * sw0[d];
        z1 += qv * sw1[d];
    }
    float g0 = 1.0f / (1.0f + expf(-z0));
    float g1 = 1.0f / (1.0f + expf(-z1));
    float gate = g0 * (g1 * gc[h] - 1.0f) + 2.0f;
    g_gate[idx] = gate;
}

// ---------------- QKV projection GEMM ----------------
// C[8192,768] = X @ W + b ; z = blockIdx.z selects (Wq,Wk,Wv).
// Output written in [b,h,s,d] layout; Q scaled by 0.125.
__global__ __launch_bounds__(256) void gemm_qkv_kernel(
    const float* __restrict__ X,
    const float* __restrict__ Wq, const float* __restrict__ bq,
    const float* __restrict__ Wk, const float* __restrict__ bk,
    const float* __restrict__ Wv, const float* __restrict__ bv)
{
    __shared__ float As[16][128];
    __shared__ float Bs[16][128];
    int z = blockIdx.z;
    const float* W    = (z == 0) ? Wq : ((z == 1) ? Wk : Wv);
    const float* bias = (z == 0) ? bq : ((z == 1) ? bk : bv);
    float* Out        = (z == 0) ? g_Q : ((z == 1) ? g_K : g_V);
    float scale = (z == 0) ? 0.125f : 1.0f;

    int bm = blockIdx.y * 128, bn = blockIdx.x * 128;
    int tid = threadIdx.x;
    int tx = tid & 15, ty = tid >> 4;

    float acc[8][8] = {};
    for (int k0 = 0; k0 < EMB; k0 += 16) {
#pragma unroll
        for (int r = 0; r < 2; r++) {
            int idx = tid + r * 256;
            int arow = idx >> 2, akq = (idx & 3) * 4;
            float4 a = *(const float4*)&X[(size_t)(bm + arow) * EMB + k0 + akq];
            As[akq + 0][arow] = a.x; As[akq + 1][arow] = a.y;
            As[akq + 2][arow] = a.z; As[akq + 3][arow] = a.w;
            int brw = idx >> 5, bcq = (idx & 31) * 4;
            *(float4*)&Bs[brw][bcq] =
                *(const float4*)&W[(size_t)(k0 + brw) * EMB + bn + bcq];
        }
        __syncthreads();
#pragma unroll
        for (int kk = 0; kk < 16; kk++) {
            float a[8], b[8];
            *(float4*)&a[0] = *(const float4*)&As[kk][ty * 8];
            *(float4*)&a[4] = *(const float4*)&As[kk][ty * 8 + 4];
            *(float4*)&b[0] = *(const float4*)&Bs[kk][tx * 8];
            *(float4*)&b[4] = *(const float4*)&Bs[kk][tx * 8 + 4];
#pragma unroll
            for (int i = 0; i < 8; i++)
#pragma unroll
                for (int j = 0; j < 8; j++)
                    acc[i][j] += a[i] * b[j];
        }
        __syncthreads();
    }
    int hcol = bn + tx * 8;
    int hh = hcol >> 6;
    int d0 = hcol & 63;
    float bb[8];
#pragma unroll
    for (int j = 0; j < 8; j++) bb[j] = bias[hcol + j];
#pragma unroll
    for (int i = 0; i < 8; i++) {
        int row = bm + ty * 8 + i;
        int b = row >> 10, sI = row & (SLEN - 1);
        float* op = Out + ((size_t)(b * NH + hh) * SLEN + sI) * HD + d0;
        float4 v0, v1;
        v0.x = (acc[i][0] + bb[0]) * scale; v0.y = (acc[i][1] + bb[1]) * scale;
        v0.z = (acc[i][2] + bb[2]) * scale; v0.w = (acc[i][3] + bb[3]) * scale;
        v1.x = (acc[i][4] + bb[4]) * scale; v1.y = (acc[i][5] + bb[5]) * scale;
        v1.z = (acc[i][6] + bb[6]) * scale; v1.w = (acc[i][7] + bb[7]) * scale;
        *(float4*)&op[0] = v0;
        *(float4*)&op[4] = v1;
    }
}

// ---------------- output projection GEMM ----------------
__global__ __launch_bounds__(256) void gemm_out_kernel(
    const float* __restrict__ Wo, const float* __restrict__ bo,
    float* __restrict__ out)
{
    __shared__ float As[16][128];
    __shared__ float Bs[16][128];
    int bm = blockIdx.y * 128, bn = blockIdx.x * 128;
    int tid = threadIdx.x;
    int tx = tid & 15, ty = tid >> 4;

    float acc[8][8] = {};
    for (int k0 = 0; k0 < EMB; k0 += 16) {
#pragma unroll
        for (int r = 0; r < 2; r++) {
            int idx = tid + r * 256;
            int arow = idx >> 2, akq = (idx & 3) * 4;
            float4 a = *(const float4*)&g_AO[(size_t)(bm + arow) * EMB + k0 + akq];
            As[akq + 0][arow] = a.x; As[akq + 1][arow] = a.y;
            As[akq + 2][arow] = a.z; As[akq + 3][arow] = a.w;
            int brw = idx >> 5, bcq = (idx & 31) * 4;
            *(float4*)&Bs[brw][bcq] =
                *(const float4*)&Wo[(size_t)(k0 + brw) * EMB + bn + bcq];
        }
        __syncthreads();
#pragma unroll
        for (int kk = 0; kk < 16; kk++) {
            float a[8], b[8];
            *(float4*)&a[0] = *(const float4*)&As[kk][ty * 8];
            *(float4*)&a[4] = *(const float4*)&As[kk][ty * 8 + 4];
            *(float4*)&b[0] = *(const float4*)&Bs[kk][tx * 8];
            *(float4*)&b[4] = *(const float4*)&Bs[kk][tx * 8 + 4];
#pragma unroll
            for (int i = 0; i < 8; i++)
#pragma unroll
                for (int j = 0; j < 8; j++)
                    acc[i][j] += a[i] * b[j];
        }
        __syncthreads();
    }
    int col = bn + tx * 8;
    float bb[8];
#pragma unroll
    for (int j = 0; j < 8; j++) bb[j] = bo[col + j];
#pragma unroll
    for (int i = 0; i < 8; i++) {
        int row = bm + ty * 8 + i;
        float4 v0, v1;
        v0.x = acc[i][0] + bb[0]; v0.y = acc[i][1] + bb[1];
        v0.z = acc[i][2] + bb[2]; v0.w = acc[i][3] + bb[3];
        v1.x = acc[i][4] + bb[4]; v1.y = acc[i][5] + bb[5];
        v1.z = acc[i][6] + bb[6]; v1.w = acc[i][7] + bb[7];
        *(float4*)&out[(size_t)row * EMB + col]     = v0;
        *(float4*)&out[(size_t)row * EMB + col + 4] = v1;
    }
}

// ---------------- flash attention ----------------
// grid: (96 = b*h, 16 = q tiles of 64). 256 threads, 4x4 microtiles.
// All smem tiles row-major with ld=68 floats (16B-aligned, 2-way worst case).
#define AT_LD 68
#define ATTN_SMEM_BYTES ((4*64*AT_LD + 64 + 32) * 4)

__global__ __launch_bounds__(256) void attn_kernel(const float* __restrict__ rel_embed)
{
    extern __shared__ float sm[];
    float* Qs = sm;                  // [64][68]
    float* Ks = Qs + 64 * AT_LD;     // [64][68]
    float* Vs = Ks + 64 * AT_LD;     // [64][68]
    float* Ps = Vs + 64 * AT_LD;     // [64][68]
    float* gate_s = Ps + 64 * AT_LD; // [64]
    float* relw   = gate_s + 64;     // [32]

    int bh = blockIdx.x;             // b*12 + h
    int qb = blockIdx.y;
    int h  = bh % NH;
    int tid = threadIdx.x;
    int tx = tid & 15, ty = tid >> 4;

    const float* Qg = g_Q + (size_t)(bh * SLEN + qb * 64) * HD;
    const float* Kg = g_K + (size_t)bh * SLEN * HD;
    const float* Vg = g_V + (size_t)bh * SLEN * HD;

#pragma unroll
    for (int r = 0; r < 4; r++) {
        int idx = tid + r * 256;
        int row = idx >> 4, dq = (idx & 15) * 4;
        *(float4*)&Qs[row * AT_LD + dq] = *(const float4*)&Qg[row * HD + dq];
    }
    if (tid < 64) gate_s[tid] = g_gate[bh * SLEN + qb * 64 + tid];
    if (tid < 32) relw[tid] = rel_embed[tid * NH + h];

    float m[4], l[4], o[4][4];
#pragma unroll
    for (int i = 0; i < 4; i++) {
        m[i] = -1e30f; l[i] = 0.0f;
#pragma unroll
        for (int j = 0; j < 4; j++) o[i][j] = 0.0f;
    }

    const unsigned char* brow = g_bucket + (size_t)(qb * 64) * SLEN;

    for (int kb = 0; kb < 16; kb++) {
        __syncthreads();   // prev PV reads done / Qs+gate visible on iter 0
#pragma unroll
        for (int r = 0; r < 4; r++) {
            int idx = tid + r * 256;
            int row = idx >> 4, dq = (idx & 15) * 4;
            *(float4*)&Ks[row * AT_LD + dq] =
                *(const float4*)&Kg[(kb * 64 + row) * HD + dq];
            *(float4*)&Vs[row * AT_LD + dq] =
                *(const float4*)&Vg[(kb * 64 + row) * HD + dq];
        }
        __syncthreads();

        // ---- scores: S = Q K^T (scale already in Q) ----
        float s[4][4] = {};
#pragma unroll 8
        for (int kk = 0; kk < HD; kk += 4) {
            float4 a[4], b[4];
#pragma unroll
            for (int i = 0; i < 4; i++)
                a[i] = *(const float4*)&Qs[(ty * 4 + i) * AT_LD + kk];
#pragma unroll
            for (int j = 0; j < 4; j++)
                b[j] = *(const float4*)&Ks[(tx * 4 + j) * AT_LD + kk];
#pragma unroll
            for (int i = 0; i < 4; i++)
#pragma unroll
                for (int j = 0; j < 4; j++)
                    s[i][j] += a[i].x * b[j].x + a[i].y * b[j].y +
                               a[i].z * b[j].z + a[i].w * b[j].w;
        }

        // ---- add gate * rel_pos_bias ----
        int kc0 = kb * 64 + tx * 4;
#pragma unroll
        for (int i = 0; i < 4; i++) {
            float g = gate_s[ty * 4 + i];
            const unsigned char* bp = brow + (size_t)(ty * 4 + i) * SLEN + kc0;
#pragma unroll
            for (int j = 0; j < 4; j++) s[i][j] += g * relw[bp[j]];
        }

        // ---- online softmax (16-lane row groups) ----
#pragma unroll
        for (int i = 0; i < 4; i++) {
            float tmax = fmaxf(fmaxf(s[i][0], s[i][1]), fmaxf(s[i][2], s[i][3]));
#pragma unroll
            for (int w = 1; w < 16; w <<= 1)
                tmax = fmaxf(tmax, __shfl_xor_sync(0xffffffffu, tmax, w));
            float mnew  = fmaxf(m[i], tmax);
            float alpha = __expf(m[i] - mnew);
            float rs = 0.0f;
#pragma unroll
            for (int j = 0; j < 4; j++) {
                s[i][j] = __expf(s[i][j] - mnew);
                rs += s[i][j];
            }
#pragma unroll
            for (int w = 1; w < 16; w <<= 1)
                rs += __shfl_xor_sync(0xffffffffu, rs, w);
            l[i] = l[i] * alpha + rs;
            m[i] = mnew;
#pragma unroll
            for (int j = 0; j < 4; j++) o[i][j] *= alpha;
        }

        // ---- P to smem ----
#pragma unroll
        for (int i = 0; i < 4; i++) {
            float4 pv = make_float4(s[i][0], s[i][1], s[i][2], s[i][3]);
            *(float4*)&Ps[(ty * 4 + i) * AT_LD + tx * 4] = pv;
        }
        __syncthreads();

        // ---- O += P V ----
#pragma unroll 4
        for (int kc = 0; kc < 64; kc += 4) {
            float4 a[4];
#pragma unroll
            for (int i = 0; i < 4; i++)
                a[i] = *(const float4*)&Ps[(ty * 4 + i) * AT_LD + kc];
#pragma unroll
            for (int t = 0; t < 4; t++) {
                float4 bv = *(const float4*)&Vs[(kc + t) * AT_LD + tx * 4];
#pragma unroll
                for (int i = 0; i < 4; i++) {
                    float av = ((const float*)&a[i])[t];
                    o[i][0] += av * bv.x;
                    o[i][1] += av * bv.y;
                    o[i][2] += av * bv.z;
                    o[i][3] += av * bv.w;
                }
            }
        }
    }

    // ---- epilogue: write [b, s, h*64+d] for the output projection ----
    int b = bh / NH;
#pragma unroll
    for (int i = 0; i < 4; i++) {
        float inv = 1.0f / l[i];
        float4 v = make_float4(o[i][0] * inv, o[i][1] * inv,
                               o[i][2] * inv, o[i][3] * inv);
        int row = qb * 64 + ty * 4 + i;
        *(float4*)&g_AO[(size_t)(b * SLEN + row) * EMB + h * HD + tx * 4] = v;
    }
}

// ---------------- launcher ----------------
extern "C" void kernel_launch(void* const* d_in, const int* in_sizes, int n_in,
                              void* d_out, int out_size)
{
    const float* query = (const float*)d_in[0];
    const float* Wq    = (const float*)d_in[1];
    const float* bq    = (const float*)d_in[2];
    const float* Wk    = (const float*)d_in[3];
    const float* bk    = (const float*)d_in[4];
    const float* Wv    = (const float*)d_in[5];
    const float* bv    = (const float*)d_in[6];
    const float* Wo    = (const float*)d_in[7];
    const float* bo    = (const float*)d_in[8];
    const float* rel   = (const float*)d_in[9];
    const float* gruW  = (const float*)d_in[10];
    const float* grub  = (const float*)d_in[11];
    const float* gruc  = (const float*)d_in[12];

    cudaFuncSetAttribute(attn_kernel,
                         cudaFuncAttributeMaxDynamicSharedMemorySize,
                         ATTN_SMEM_BYTES);

    bucket_kernel<<<dim3(4, SLEN), 256>>>();
    gate_kernel<<<BATCH * NH * SLEN / 256, 256>>>(query, gruW, grub, gruc);
    gemm_qkv_kernel<<<dim3(EMB / 128, MROWS / 128, 3), 256>>>(
        query, Wq, bq, Wk, bk, Wv, bv);
    attn_kernel<<<dim3(BATCH * NH, SLEN / 64), 256, ATTN_SMEM_BYTES>>>(rel);
    gemm_out_kernel<<<dim3(EMB / 128, MROWS / 128), 256>>>(
        Wo, bo, (float*)d_out);
}